// round 1
// baseline (speedup 1.0000x reference)
#include <cuda_runtime.h>

// Problem shape (fixed by reference setup_inputs)
#define B_   16
#define Y_   32
#define H_   256
#define W_   256
#define HW_  (H_ * W_)            // 65536
#define NPIX (B_ * HW_)           // 1048576
#define THREADS 256
#define NBLOCKS (NPIX / THREADS)  // 4096
#define DIST_IND 7.0f

__device__ double g_partials[NBLOCKS];

__device__ __forceinline__ void regress_f(float n, float sx, float sxx,
                                          float sy, float sxy,
                                          float& slope, float& inter, bool& valid) {
    valid = (n >= 3.0f);
    float ns  = fmaxf(n, 1.0f);
    float cov = sxy - sx * sy / ns;
    float var = sxx - sx * sx / ns;
    float vs  = (var > 0.0f) ? var : 1.0f;
    float s   = cov / vs;
    s = fminf(fmaxf(s, 0.0f), 2.0f);   // clip(0, 2)
    slope = s;
    inter = (sy - s * sx) / ns;
}

__global__ void __launch_bounds__(THREADS)
disturbance_loss_kernel(const float* __restrict__ out) {
    int p  = blockIdx.x * THREADS + threadIdx.x;   // pixel id in [0, NPIX)
    int b  = p >> 16;                               // p / HW_
    int hw = p & (HW_ - 1);
    const float* base = out + (size_t)b * (Y_ * HW_) + hw;

    // Load full Y-column into registers (coalesced across lanes; 32 independent
    // loads -> high MLP, one pass over the data).
    float v[Y_];
#pragma unroll
    for (int y = 0; y < Y_; ++y)
        v[y] = __ldg(base + y * HW_);

    // argmin of diff: diff[0] = -DIST_IND, diff[1]=diff[31]=0 (never < -7),
    // diff[y]=v[y]-v[y-1] for y in [2,30]. Strict < preserves first-occurrence.
    float best = -DIST_IND;
    int   f    = 0;
#pragma unroll
    for (int y = 2; y <= Y_ - 2; ++y) {
        float d = v[y] - v[y - 1];
        if (d < best) { best = d; f = y; }
    }
    float ff = (float)f;

    // Data-dependent sums for both segments.
    float sy_b = 0.f, sxy_b = 0.f, sy_a = 0.f, sxy_a = 0.f;
#pragma unroll
    for (int t = 0; t < Y_; ++t) {
        float tv = (float)t;
        if (t < f) { sy_b += v[t]; sxy_b += tv * v[t]; }
        else       { sy_a += v[t]; sxy_a += (tv - ff) * v[t]; }
    }

    // Closed-form n, sx, sxx from the split index.
    int m = Y_ - f;
    float n_b   = (float)f;
    float sx_b  = (float)(f * (f - 1) / 2);
    float sxx_b = (float)((f - 1) * f * (2 * f - 1) / 6);
    float n_a   = (float)m;
    float sx_a  = (float)(m * (m - 1) / 2);
    float sxx_a = (float)((m - 1) * m * (2 * m - 1) / 6);

    float slope_b, int_b, slope_a, int_a;
    bool  val_b, val_a;
    regress_f(n_b, sx_b, sxx_b, sy_b, sxy_b, slope_b, int_b, val_b);
    regress_f(n_a, sx_a, sxx_a, sy_a, sxy_a, slope_a, int_a, val_a);

    // Residuals (reuse register-resident v[]).
    float res_b = 0.f, res_a = 0.f;
#pragma unroll
    for (int t = 0; t < Y_; ++t) {
        float tv = (float)t;
        if (t < f) { float r = v[t] - (slope_b * tv + int_b);          res_b += r * r; }
        else       { float r = v[t] - (slope_a * (tv - ff) + int_a);   res_a += r * r; }
    }

    float contrib = (val_b ? res_b : 0.f) + (val_a ? res_a : 0.f);

    // Deterministic per-block reduction.
    __shared__ float sdata[THREADS];
    sdata[threadIdx.x] = contrib;
    __syncthreads();
#pragma unroll
    for (int s = THREADS / 2; s > 0; s >>= 1) {
        if (threadIdx.x < s) sdata[threadIdx.x] += sdata[threadIdx.x + s];
        __syncthreads();
    }
    if (threadIdx.x == 0)
        g_partials[blockIdx.x] = (double)sdata[0];
}

__global__ void __launch_bounds__(256)
final_reduce_kernel(float* __restrict__ d_out) {
    __shared__ double sd[256];
    double s = 0.0;
    for (int i = threadIdx.x; i < NBLOCKS; i += 256)
        s += g_partials[i];
    sd[threadIdx.x] = s;
    __syncthreads();
#pragma unroll
    for (int k = 128; k > 0; k >>= 1) {
        if (threadIdx.x < k) sd[threadIdx.x] += sd[threadIdx.x + k];
        __syncthreads();
    }
    if (threadIdx.x == 0)
        d_out[0] = (float)(sd[0] / ((double)Y_ * (double)NPIX));
}

extern "C" void kernel_launch(void* const* d_in, const int* in_sizes, int n_in,
                              void* d_out, int out_size) {
    const float* out = (const float*)d_in[0];   // 'out' tensor; 'target' (d_in[1]) is unused by the reference
    (void)in_sizes; (void)n_in; (void)out_size;

    disturbance_loss_kernel<<<NBLOCKS, THREADS>>>(out);
    final_reduce_kernel<<<1, 256>>>((float*)d_out);
}

// round 2
// speedup vs baseline: 1.1319x; 1.1319x over previous
#include <cuda_runtime.h>

// Problem shape (fixed by reference setup_inputs)
#define B_   16
#define Y_   32
#define H_   256
#define W_   256
#define HW_  (H_ * W_)            // 65536
#define NPIX (B_ * HW_)           // 1048576
#define THREADS 256
#define PPT 4                     // pixels per thread (float4)
#define NBLOCKS (NPIX / (THREADS * PPT))  // 1024
#define DIST_IND 7.0f

__device__ double g_partials[NBLOCKS];
__device__ unsigned int g_count = 0;

__global__ void __launch_bounds__(THREADS)
disturbance_loss_fused(const float* __restrict__ out, float* __restrict__ d_out) {
    const int gt = blockIdx.x * THREADS + threadIdx.x;
    const int p4 = gt * PPT;                 // first of 4 adjacent pixels
    const int b  = p4 >> 16;                 // p4 / HW_
    const int hw = p4 & (HW_ - 1);
    const float4* __restrict__ base =
        (const float4*)(out + (size_t)b * (Y_ * HW_) + hw);
    const int rs = HW_ / 4;                  // row stride in float4 (16384)

    // Streaming state per pixel lane: running sums (T*), snapshots at the
    // current best split (s*), argmin tracker.
    float T0[PPT], T1[PPT], T2[PPT];         // sum v, sum t*v, sum v^2 over t<y
    float s0[PPT], s1[PPT], s2[PPT];         // snapshots at t<f
    float best[PPT], prev[PPT];
    int   f[PPT];
#pragma unroll
    for (int j = 0; j < PPT; ++j) {
        T0[j] = T1[j] = T2[j] = 0.f;
        s0[j] = s1[j] = s2[j] = 0.f;
        best[j] = -DIST_IND; prev[j] = 0.f; f[j] = 0;
    }

#pragma unroll
    for (int y = 0; y < Y_; ++y) {
        float4 v4 = __ldg(&base[y * rs]);
        float vv[PPT] = {v4.x, v4.y, v4.z, v4.w};
        float yf = (float)y;
#pragma unroll
        for (int j = 0; j < PPT; ++j) {
            float v = vv[j];
            if (y >= 2 && y <= Y_ - 2) {     // diff defined/nonzero only here
                float d = v - prev[j];
                if (d < best[j]) {           // strict < = first occurrence
                    best[j] = d; f[j] = y;
                    s0[j] = T0[j]; s1[j] = T1[j]; s2[j] = T2[j];
                }
            }
            T0[j] += v;
            T1[j] += yf * v;
            T2[j] += v * v;
            prev[j] = v;
        }
    }

    float contrib = 0.f;
#pragma unroll
    for (int j = 0; j < PPT; ++j) {
        int   fi = f[j];
        float ff = (float)fi;
        int   m  = Y_ - fi;

        // before segment: x = t, t in [0, f)
        float n_b   = ff;
        float sx_b  = (float)(fi * (fi - 1) / 2);
        float sxx_b = (float)((fi - 1) * fi * (2 * fi - 1) / 6);
        float sy_b  = s0[j];
        float sxy_b = s1[j];
        float syy_b = s2[j];

        // after segment: x = t - f, t in [f, Y)
        float n_a   = (float)m;
        float sx_a  = (float)(m * (m - 1) / 2);
        float sxx_a = (float)((m - 1) * m * (2 * m - 1) / 6);
        float sy_a  = T0[j] - s0[j];
        float sxy_a = (T1[j] - s1[j]) - ff * sy_a;
        float syy_a = T2[j] - s2[j];

        // regress (before)
        {
            float ns  = fmaxf(n_b, 1.0f);
            float cov = sxy_b - sx_b * sy_b / ns;
            float var = sxx_b - sx_b * sx_b / ns;
            float vs  = (var > 0.f) ? var : 1.f;
            float s   = fminf(fmaxf(cov / vs, 0.f), 2.f);
            float c   = (sy_b - s * sx_b) / ns;
            float res = syy_b - 2.f * s * sxy_b - 2.f * c * sy_b
                      + s * s * sxx_b + 2.f * s * c * sx_b + c * c * n_b;
            if (n_b >= 3.f) contrib += res;
        }
        // regress (after)
        {
            float ns  = fmaxf(n_a, 1.0f);
            float cov = sxy_a - sx_a * sy_a / ns;
            float var = sxx_a - sx_a * sx_a / ns;
            float vs  = (var > 0.f) ? var : 1.f;
            float s   = fminf(fmaxf(cov / vs, 0.f), 2.f);
            float c   = (sy_a - s * sx_a) / ns;
            float res = syy_a - 2.f * s * sxy_a - 2.f * c * sy_a
                      + s * s * sxx_a + 2.f * s * c * sx_a + c * c * n_a;
            if (n_a >= 3.f) contrib += res;
        }
    }

    // ---- deterministic in-block reduction (warp shuffles, fixed order) ----
    unsigned lane = threadIdx.x & 31u;
    unsigned wid  = threadIdx.x >> 5;
    float w = contrib;
#pragma unroll
    for (int o = 16; o > 0; o >>= 1)
        w += __shfl_down_sync(0xFFFFFFFFu, w, o);

    __shared__ float warpsum[THREADS / 32];
    if (lane == 0) warpsum[wid] = w;
    __syncthreads();

    __shared__ bool is_last;
    if (wid == 0) {
        float t = (lane < THREADS / 32) ? warpsum[lane] : 0.f;
#pragma unroll
        for (int o = 4; o > 0; o >>= 1)
            t += __shfl_down_sync(0xFFFFFFFFu, t, o);
        if (lane == 0) {
            g_partials[blockIdx.x] = (double)t;
            __threadfence();
            unsigned done = atomicAdd(&g_count, 1u);
            is_last = (done == (unsigned)(NBLOCKS - 1));
        }
    }
    __syncthreads();

    // ---- last block sums all partials in fixed index order (deterministic) ----
    if (is_last) {
        __threadfence();
        double s = 0.0;
#pragma unroll
        for (int k = 0; k < NBLOCKS / THREADS; ++k)
            s += g_partials[threadIdx.x + k * THREADS];
#pragma unroll
        for (int o = 16; o > 0; o >>= 1)
            s += __shfl_down_sync(0xFFFFFFFFu, s, o);
        __shared__ double wsum[THREADS / 32];
        if (lane == 0) wsum[wid] = s;
        __syncthreads();
        if (wid == 0) {
            double t = (lane < THREADS / 32) ? wsum[lane] : 0.0;
#pragma unroll
            for (int o = 4; o > 0; o >>= 1)
                t += __shfl_down_sync(0xFFFFFFFFu, t, o);
            if (lane == 0) {
                d_out[0] = (float)(t / ((double)Y_ * (double)NPIX));
                g_count = 0;   // reset for next graph replay
            }
        }
    }
}

extern "C" void kernel_launch(void* const* d_in, const int* in_sizes, int n_in,
                              void* d_out, int out_size) {
    const float* out = (const float*)d_in[0];   // 'target' (d_in[1]) unused by reference
    (void)in_sizes; (void)n_in; (void)out_size;
    disturbance_loss_fused<<<NBLOCKS, THREADS>>>(out, (float*)d_out);
}

// round 3
// speedup vs baseline: 1.3370x; 1.1812x over previous
#include <cuda_runtime.h>

// Problem shape (fixed by reference setup_inputs)
#define B_   16
#define Y_   32
#define H_   256
#define W_   256
#define HW_  (H_ * W_)            // 65536
#define NPIX (B_ * HW_)           // 1048576
#define THREADS 256
#define PPT 2                     // pixels per thread (float2 loads)
#define NBLOCKS (NPIX / (THREADS * PPT))  // 2048
#define CHUNK 8                   // rows prefetched per batch (MLP)
#define DIST_IND 7.0f

__device__ double g_partials[NBLOCKS];
__device__ unsigned int g_count = 0;

__global__ void __launch_bounds__(THREADS, 4)
disturbance_loss_fused(const float* __restrict__ out, float* __restrict__ d_out) {
    const int gt = blockIdx.x * THREADS + threadIdx.x;
    const int p2 = gt * PPT;                 // first of 2 adjacent pixels
    const int b  = p2 >> 16;                 // p2 / HW_
    const int hw = p2 & (HW_ - 1);
    const float2* __restrict__ base =
        (const float2*)(out + (size_t)b * (Y_ * HW_) + hw);
    const int rs = HW_ / 2;                  // row stride in float2 (32768)

    // Streaming state per pixel lane.
    float T0[PPT], T1[PPT], T2[PPT];         // running sums: v, t*v, v*v
    float s0[PPT], s1[PPT], s2[PPT];         // snapshots at current best split
    float best[PPT], prev[PPT];
    int   f[PPT];
#pragma unroll
    for (int j = 0; j < PPT; ++j) {
        T0[j] = T1[j] = T2[j] = 0.f;
        s0[j] = s1[j] = s2[j] = 0.f;
        best[j] = -DIST_IND; prev[j] = 0.f; f[j] = 0;
    }

#pragma unroll
    for (int yc = 0; yc < Y_; yc += CHUNK) {
        // Front-batched loads: 8 outstanding LDG.64 before any consumption.
        float2 buf[CHUNK];
#pragma unroll
        for (int i = 0; i < CHUNK; ++i)
            buf[i] = __ldg(&base[(yc + i) * rs]);

#pragma unroll
        for (int i = 0; i < CHUNK; ++i) {
            const int y = yc + i;            // compile-time constant
            const float yf = (float)y;
            float vv[PPT] = {buf[i].x, buf[i].y};
#pragma unroll
            for (int j = 0; j < PPT; ++j) {
                float v = vv[j];
                if (y >= 2 && y <= Y_ - 2) {
                    float d = v - prev[j];
                    bool pr = (d < best[j]);         // off critical path
                    best[j] = fminf(best[j], d);     // FMNMX: 4-cyc loop carry
                    f[j]  = pr ? y     : f[j];
                    s0[j] = pr ? T0[j] : s0[j];
                    s1[j] = pr ? T1[j] : s1[j];
                    s2[j] = pr ? T2[j] : s2[j];
                }
                T0[j] += v;
                T1[j] = fmaf(yf, v, T1[j]);
                T2[j] = fmaf(v, v, T2[j]);
                prev[j] = v;
            }
        }
    }

    float contrib = 0.f;
#pragma unroll
    for (int j = 0; j < PPT; ++j) {
        int   fi = f[j];
        float ff = (float)fi;
        int   m  = Y_ - fi;

        // before segment: x = t, t in [0, f)
        float n_b   = ff;
        float sx_b  = (float)(fi * (fi - 1) / 2);
        float sxx_b = (float)((fi - 1) * fi * (2 * fi - 1) / 6);
        float sy_b  = s0[j];
        float sxy_b = s1[j];
        float syy_b = s2[j];

        // after segment: x = t - f, t in [f, Y)
        float n_a   = (float)m;
        float sx_a  = (float)(m * (m - 1) / 2);
        float sxx_a = (float)((m - 1) * m * (2 * m - 1) / 6);
        float sy_a  = T0[j] - s0[j];
        float sxy_a = (T1[j] - s1[j]) - ff * sy_a;
        float syy_a = T2[j] - s2[j];

        {   // regress + residual (before)
            float ns  = fmaxf(n_b, 1.0f);
            float cov = sxy_b - sx_b * sy_b / ns;
            float var = sxx_b - sx_b * sx_b / ns;
            float vs  = (var > 0.f) ? var : 1.f;
            float s   = fminf(fmaxf(cov / vs, 0.f), 2.f);
            float c   = (sy_b - s * sx_b) / ns;
            float res = syy_b - 2.f * s * sxy_b - 2.f * c * sy_b
                      + s * s * sxx_b + 2.f * s * c * sx_b + c * c * n_b;
            if (n_b >= 3.f) contrib += res;
        }
        {   // regress + residual (after)
            float ns  = fmaxf(n_a, 1.0f);
            float cov = sxy_a - sx_a * sy_a / ns;
            float var = sxx_a - sx_a * sx_a / ns;
            float vs  = (var > 0.f) ? var : 1.f;
            float s   = fminf(fmaxf(cov / vs, 0.f), 2.f);
            float c   = (sy_a - s * sx_a) / ns;
            float res = syy_a - 2.f * s * sxy_a - 2.f * c * sy_a
                      + s * s * sxx_a + 2.f * s * c * sx_a + c * c * n_a;
            if (n_a >= 3.f) contrib += res;
        }
    }

    // ---- deterministic in-block reduction ----
    unsigned lane = threadIdx.x & 31u;
    unsigned wid  = threadIdx.x >> 5;
    float w = contrib;
#pragma unroll
    for (int o = 16; o > 0; o >>= 1)
        w += __shfl_down_sync(0xFFFFFFFFu, w, o);

    __shared__ float warpsum[THREADS / 32];
    if (lane == 0) warpsum[wid] = w;
    __syncthreads();

    __shared__ bool is_last;
    if (wid == 0) {
        float t = (lane < THREADS / 32) ? warpsum[lane] : 0.f;
#pragma unroll
        for (int o = 4; o > 0; o >>= 1)
            t += __shfl_down_sync(0xFFFFFFFFu, t, o);
        if (lane == 0) {
            g_partials[blockIdx.x] = (double)t;
            __threadfence();
            unsigned done = atomicAdd(&g_count, 1u);
            is_last = (done == (unsigned)(NBLOCKS - 1));
        }
    }
    __syncthreads();

    // ---- last block sums all partials in fixed index order (deterministic) ----
    if (is_last) {
        __threadfence();
        double s = 0.0;
#pragma unroll
        for (int k = 0; k < NBLOCKS / THREADS; ++k)
            s += g_partials[threadIdx.x + k * THREADS];
#pragma unroll
        for (int o = 16; o > 0; o >>= 1)
            s += __shfl_down_sync(0xFFFFFFFFu, s, o);
        __shared__ double wsum[THREADS / 32];
        if (lane == 0) wsum[wid] = s;
        __syncthreads();
        if (wid == 0) {
            double t = (lane < THREADS / 32) ? wsum[lane] : 0.0;
#pragma unroll
            for (int o = 4; o > 0; o >>= 1)
                t += __shfl_down_sync(0xFFFFFFFFu, t, o);
            if (lane == 0) {
                d_out[0] = (float)(t / ((double)Y_ * (double)NPIX));
                g_count = 0;   // reset for next graph replay
            }
        }
    }
}

extern "C" void kernel_launch(void* const* d_in, const int* in_sizes, int n_in,
                              void* d_out, int out_size) {
    const float* out = (const float*)d_in[0];   // 'target' (d_in[1]) unused by reference
    (void)in_sizes; (void)n_in; (void)out_size;
    disturbance_loss_fused<<<NBLOCKS, THREADS>>>(out, (float*)d_out);
}